// round 6
// baseline (speedup 1.0000x reference)
#include <cuda_runtime.h>

#define N_NODES 100000
#define N_EDGES 3200000
#define TB 256

// ---- persistent device scratch (no allocations allowed) ----
__device__ int      g_deg [N_NODES];
__device__ float    g_dinv[N_NODES];
__device__ float    g_xn  [N_NODES * 4];   // x * dinv
__device__ float    g_agg [N_NODES * 4];   // un-dst-normalized layer-1 aggregate
__device__ float    g_tn  [N_NODES * 2];   // t * dinv
__device__ unsigned g_bar [8];             // grid-barrier counters (memset to 0 pre-launch)

// Vectorized no-return global reductions.
__device__ __forceinline__ void red_add_v4(float* p, float a, float b, float c, float d) {
    asm volatile("red.global.add.v4.f32 [%0], {%1,%2,%3,%4};"
                 :: "l"(p), "f"(a), "f"(b), "f"(c), "f"(d) : "memory");
}
__device__ __forceinline__ void red_add_v2(float* p, float a, float b) {
    asm volatile("red.global.add.v2.f32 [%0], {%1,%2};"
                 :: "l"(p), "f"(a), "f"(b) : "memory");
}
__device__ __forceinline__ void red_add_u32(int* p) {
    asm volatile("red.global.add.u32 [%0], 1;" :: "l"(p) : "memory");
}

// CG-style grid barrier: block arrives with release semantics, thread 0 polls
// with acquire loads, __syncthreads() fans out to the block.
__device__ __forceinline__ void grid_bar(int k) {
    __syncthreads();
    if (threadIdx.x == 0) {
        unsigned G = gridDim.x;
        asm volatile("red.release.gpu.global.add.u32 [%0], 1;"
                     :: "l"(&g_bar[k]) : "memory");
        unsigned v;
        do {
            asm volatile("ld.global.acquire.gpu.u32 %0, [%1];"
                         : "=r"(v) : "l"(&g_bar[k]) : "memory");
        } while (v < G);
    }
    __syncthreads();
}

__global__ void __launch_bounds__(TB, 6)
k_fused(const float* __restrict__ x,
        const int* __restrict__ src, const int* __restrict__ dst,
        const float* __restrict__ W1, const float* __restrict__ b1,
        const float* __restrict__ W2, const float* __restrict__ b2,
        float* __restrict__ out) {
    const int g      = blockIdx.x * TB + threadIdx.x;
    const int stride = gridDim.x * TB;

    // ---- P0: zero degree accumulator ----
    for (int i = g; i < N_NODES; i += stride)
        g_deg[i] = 0;
    grid_bar(0);

    // ---- P1: degree of dst endpoints (4 edges / iter, int4-coalesced) ----
    for (int i = g; i < N_EDGES / 4; i += stride) {
        int4 d = __ldg(&reinterpret_cast<const int4*>(dst)[i]);
        red_add_u32(&g_deg[d.x]);
        red_add_u32(&g_deg[d.y]);
        red_add_u32(&g_deg[d.z]);
        red_add_u32(&g_deg[d.w]);
    }
    grid_bar(1);

    // ---- P2: dinv = rsqrt(deg+1); xn = x*dinv; zero agg (folded) ----
    for (int i = g; i < N_NODES; i += stride) {
        float di = rsqrtf((float)(g_deg[i] + 1));
        g_dinv[i] = di;
        float4 xv = __ldg(&reinterpret_cast<const float4*>(x)[i]);
        reinterpret_cast<float4*>(g_xn)[i] =
            make_float4(xv.x * di, xv.y * di, xv.z * di, xv.w * di);
        reinterpret_cast<float4*>(g_agg)[i] = make_float4(0.f, 0.f, 0.f, 0.f);
    }
    grid_bar(2);

    // ---- P3: layer-1 edges: agg[dst] += xn[src]  (dst factor deferred) ----
    {
        const float4* xv = reinterpret_cast<const float4*>(g_xn);
        for (int i = g; i < N_EDGES / 4; i += stride) {
            int4 s = __ldg(&reinterpret_cast<const int4*>(src)[i]);
            int4 d = __ldg(&reinterpret_cast<const int4*>(dst)[i]);
            float4 v0 = __ldg(&xv[s.x]);
            float4 v1 = __ldg(&xv[s.y]);
            float4 v2 = __ldg(&xv[s.z]);
            float4 v3 = __ldg(&xv[s.w]);
            red_add_v4(&g_agg[4 * d.x], v0.x, v0.y, v0.z, v0.w);
            red_add_v4(&g_agg[4 * d.y], v1.x, v1.y, v1.z, v1.w);
            red_add_v4(&g_agg[4 * d.z], v2.x, v2.y, v2.z, v2.w);
            red_add_v4(&g_agg[4 * d.w], v3.x, v3.y, v3.z, v3.w);
        }
    }
    grid_bar(3);

    // ---- P4: per-node transform; tn = (relu((dinv*agg + x*dinv^2)W1+b1)W2)*dinv;
    //          out init = tn (self-loop contribution pre-dst-scale) ----
    for (int v = g; v < N_NODES; v += stride) {
        float di = g_dinv[v];
        float sl = di * di;
        float4 xv = __ldg(&reinterpret_cast<const float4*>(x)[v]);
        float4 ag = reinterpret_cast<const float4*>(g_agg)[v];
        float a0 = ag.x * di + xv.x * sl;
        float a1 = ag.y * di + xv.y * sl;
        float a2 = ag.z * di + xv.z * sl;
        float a3 = ag.w * di + xv.w * sl;

        float t0 = 0.f, t1 = 0.f;
        #pragma unroll
        for (int j = 0; j < 16; j++) {
            float h = a0 * __ldg(&W1[j])      + a1 * __ldg(&W1[16 + j])
                    + a2 * __ldg(&W1[32 + j]) + a3 * __ldg(&W1[48 + j]) + __ldg(&b1[j]);
            h = fmaxf(h, 0.f);
            t0 += h * __ldg(&W2[2 * j]);
            t1 += h * __ldg(&W2[2 * j + 1]);
        }
        float tn0 = t0 * di, tn1 = t1 * di;
        reinterpret_cast<float2*>(g_tn)[v] = make_float2(tn0, tn1);
        reinterpret_cast<float2*>(out)[v]  = make_float2(tn0, tn1);
    }
    grid_bar(4);

    // ---- P5: layer-2 edges: out[dst] += tn[src]  (dst factor deferred) ----
    {
        const float2* tv = reinterpret_cast<const float2*>(g_tn);
        for (int i = g; i < N_EDGES / 4; i += stride) {
            int4 s = __ldg(&reinterpret_cast<const int4*>(src)[i]);
            int4 d = __ldg(&reinterpret_cast<const int4*>(dst)[i]);
            float2 t0 = __ldg(&tv[s.x]);
            float2 t1 = __ldg(&tv[s.y]);
            float2 t2 = __ldg(&tv[s.z]);
            float2 t3 = __ldg(&tv[s.w]);
            red_add_v2(&out[2 * d.x], t0.x, t0.y);
            red_add_v2(&out[2 * d.y], t1.x, t1.y);
            red_add_v2(&out[2 * d.z], t2.x, t2.y);
            red_add_v2(&out[2 * d.w], t3.x, t3.y);
        }
    }
    grid_bar(5);

    // ---- P6: apply deferred dst factor + bias ----
    {
        float c0 = __ldg(&b2[0]);
        float c1 = __ldg(&b2[1]);
        for (int v = g; v < N_NODES; v += stride) {
            float di = g_dinv[v];
            float2 o = reinterpret_cast<float2*>(out)[v];
            reinterpret_cast<float2*>(out)[v] =
                make_float2(o.x * di + c0, o.y * di + c1);
        }
    }
}

extern "C" void kernel_launch(void* const* d_in, const int* in_sizes, int n_in,
                              void* d_out, int out_size) {
    const float* x   = (const float*)d_in[0];     // [N, 4]
    const int*   ei  = (const int*)  d_in[1];     // [2, E]
    const float* W1  = (const float*)d_in[2];     // [4, 16]
    const float* b1  = (const float*)d_in[3];     // [16]
    const float* W2  = (const float*)d_in[4];     // [16, 2]
    const float* b2  = (const float*)d_in[5];     // [2]
    float* out = (float*)d_out;                   // [N, 2]

    const int* src = ei;
    const int* dst = ei + N_EDGES;

    // Co-resident grid: SMs * max-active-blocks (what cooperative launch would use).
    int dev = 0, sm = 0, maxb = 0;
    cudaGetDevice(&dev);
    cudaDeviceGetAttribute(&sm, cudaDevAttrMultiProcessorCount, dev);
    cudaOccupancyMaxActiveBlocksPerMultiprocessor(&maxb, k_fused, TB, 0);
    if (maxb < 1) maxb = 1;
    int grid = sm * maxb;

    // Reset barrier counters (memset node in the captured graph; no allocation).
    void* barp = nullptr;
    cudaGetSymbolAddress(&barp, g_bar);
    cudaMemsetAsync(barp, 0, 8 * sizeof(unsigned));

    k_fused<<<grid, TB>>>(x, src, dst, W1, b1, W2, b2, out);
}

// round 7
// speedup vs baseline: 1.2496x; 1.2496x over previous
#include <cuda_runtime.h>

#define N_NODES 100000
#define N_EDGES 3200000

// ---- persistent device scratch (no allocations allowed) ----
__device__ int   g_deg [N_NODES];
__device__ float g_dinv[N_NODES];
__device__ float g_xn  [N_NODES * 4];   // x * dinv  (src-normalized features)
__device__ float g_agg [N_NODES * 4];   // un-dst-normalized layer-1 aggregate
__device__ float g_tn  [N_NODES * 2];   // t * dinv  (src-normalized layer-2 features)

// Vectorized no-return global reductions (one L2 message per 2/4 floats).
__device__ __forceinline__ void red_add_v4(float* p, float a, float b, float c, float d) {
    asm volatile("red.global.add.v4.f32 [%0], {%1,%2,%3,%4};"
                 :: "l"(p), "f"(a), "f"(b), "f"(c), "f"(d) : "memory");
}
__device__ __forceinline__ void red_add_v2(float* p, float a, float b) {
    asm volatile("red.global.add.v2.f32 [%0], {%1,%2};"
                 :: "l"(p), "f"(a), "f"(b) : "memory");
}
__device__ __forceinline__ void red_add_u32(int* p) {
    asm volatile("red.global.add.u32 [%0], 1;" :: "l"(p) : "memory");
}

// K1: degree of dst endpoints (4 edges / thread, int4-coalesced)
__global__ void k_deg(const int* __restrict__ dst) {
    int i = blockIdx.x * blockDim.x + threadIdx.x;
    if (i < N_EDGES / 4) {
        int4 d = __ldg(&reinterpret_cast<const int4*>(dst)[i]);
        red_add_u32(&g_deg[d.x]);
        red_add_u32(&g_deg[d.y]);
        red_add_u32(&g_deg[d.z]);
        red_add_u32(&g_deg[d.w]);
    }
}

// K2: dinv = rsqrt(deg+1);  xn = x * dinv
__global__ void k_dinv_xn(const float* __restrict__ x) {
    int i = blockIdx.x * blockDim.x + threadIdx.x;
    if (i >= N_NODES) return;
    float di = rsqrtf((float)(g_deg[i] + 1));
    g_dinv[i] = di;
    float4 xv = __ldg(&reinterpret_cast<const float4*>(x)[i]);
    reinterpret_cast<float4*>(g_xn)[i] =
        make_float4(xv.x * di, xv.y * di, xv.z * di, xv.w * di);
}

// K3: layer-1 edges: agg[dst] += xn[src]  (dst factor deferred)
// Gathers use __ldcg (L2-only, no L1 allocate: random access, L2-resident set).
__global__ void k_l1_edges(const int* __restrict__ src, const int* __restrict__ dst) {
    int i = blockIdx.x * blockDim.x + threadIdx.x;
    if (i >= N_EDGES / 4) return;
    int4 s = __ldg(&reinterpret_cast<const int4*>(src)[i]);
    int4 d = __ldg(&reinterpret_cast<const int4*>(dst)[i]);
    const float4* xv = reinterpret_cast<const float4*>(g_xn);

    float4 v0 = __ldcg(&xv[s.x]);
    float4 v1 = __ldcg(&xv[s.y]);
    float4 v2 = __ldcg(&xv[s.z]);
    float4 v3 = __ldcg(&xv[s.w]);
    red_add_v4(&g_agg[4 * d.x], v0.x, v0.y, v0.z, v0.w);
    red_add_v4(&g_agg[4 * d.y], v1.x, v1.y, v1.z, v1.w);
    red_add_v4(&g_agg[4 * d.z], v2.x, v2.y, v2.z, v2.w);
    red_add_v4(&g_agg[4 * d.w], v3.x, v3.y, v3.z, v3.w);
}

// K4: per-node transform.
//   a  = dinv*agg + x*dinv^2 ; h = relu(a@W1+b1); t = h@W2; tn = t*dinv
//   out-accumulator init = tn  (self-loop contribution pre-dst-scale)
__global__ void k_xform(const float* __restrict__ x,
                        const float* __restrict__ W1, const float* __restrict__ b1,
                        const float* __restrict__ W2,
                        float* __restrict__ out) {
    int v = blockIdx.x * blockDim.x + threadIdx.x;
    if (v >= N_NODES) return;
    float di = g_dinv[v];
    float sl = di * di;
    float4 xv = __ldg(&reinterpret_cast<const float4*>(x)[v]);
    float4 ag = reinterpret_cast<const float4*>(g_agg)[v];
    float a0 = ag.x * di + xv.x * sl;
    float a1 = ag.y * di + xv.y * sl;
    float a2 = ag.z * di + xv.z * sl;
    float a3 = ag.w * di + xv.w * sl;

    float t0 = 0.f, t1 = 0.f;
    #pragma unroll
    for (int j = 0; j < 16; j++) {
        float h = a0 * __ldg(&W1[j])      + a1 * __ldg(&W1[16 + j])
                + a2 * __ldg(&W1[32 + j]) + a3 * __ldg(&W1[48 + j]) + __ldg(&b1[j]);
        h = fmaxf(h, 0.f);
        t0 += h * __ldg(&W2[2 * j]);
        t1 += h * __ldg(&W2[2 * j + 1]);
    }
    float tn0 = t0 * di, tn1 = t1 * di;
    reinterpret_cast<float2*>(g_tn)[v] = make_float2(tn0, tn1);
    reinterpret_cast<float2*>(out)[v]  = make_float2(tn0, tn1);  // self-loop init
}

// K5: layer-2 edges: out[dst] += tn[src]  (dst factor deferred)
__global__ void k_l2_edges(const int* __restrict__ src, const int* __restrict__ dst,
                           float* __restrict__ out) {
    int i = blockIdx.x * blockDim.x + threadIdx.x;
    if (i >= N_EDGES / 4) return;
    int4 s = __ldg(&reinterpret_cast<const int4*>(src)[i]);
    int4 d = __ldg(&reinterpret_cast<const int4*>(dst)[i]);
    const float2* tv = reinterpret_cast<const float2*>(g_tn);

    float2 t0 = __ldcg(&tv[s.x]);
    float2 t1 = __ldcg(&tv[s.y]);
    float2 t2 = __ldcg(&tv[s.z]);
    float2 t3 = __ldcg(&tv[s.w]);
    red_add_v2(&out[2 * d.x], t0.x, t0.y);
    red_add_v2(&out[2 * d.y], t1.x, t1.y);
    red_add_v2(&out[2 * d.z], t2.x, t2.y);
    red_add_v2(&out[2 * d.w], t3.x, t3.y);
}

// K6: apply deferred dst factor + bias:  out = out*dinv + b2
__global__ void k_finish(float* __restrict__ out, const float* __restrict__ b2) {
    int v = blockIdx.x * blockDim.x + threadIdx.x;
    if (v >= N_NODES) return;
    float di = g_dinv[v];
    float2 o = reinterpret_cast<float2*>(out)[v];
    reinterpret_cast<float2*>(out)[v] =
        make_float2(o.x * di + __ldg(&b2[0]), o.y * di + __ldg(&b2[1]));
}

extern "C" void kernel_launch(void* const* d_in, const int* in_sizes, int n_in,
                              void* d_out, int out_size) {
    const float* x   = (const float*)d_in[0];     // [N, 4]
    const int*   ei  = (const int*)  d_in[1];     // [2, E]
    const float* W1  = (const float*)d_in[2];     // [4, 16]
    const float* b1  = (const float*)d_in[3];     // [16]
    const float* W2  = (const float*)d_in[4];     // [16, 2]
    const float* b2  = (const float*)d_in[5];     // [2]
    float* out = (float*)d_out;                   // [N, 2]

    const int* src = ei;
    const int* dst = ei + N_EDGES;

    const int TB = 256;
    int nodeBlocks = (N_NODES + TB - 1) / TB;
    int edgeBlocks = (N_EDGES / 4 + TB - 1) / TB;

    // Zero accumulators with DMA memset nodes instead of a kernel.
    void* degp = nullptr; void* aggp = nullptr;
    cudaGetSymbolAddress(&degp, g_deg);
    cudaGetSymbolAddress(&aggp, g_agg);
    cudaMemsetAsync(degp, 0, N_NODES * sizeof(int));
    cudaMemsetAsync(aggp, 0, N_NODES * 4 * sizeof(float));

    k_deg     <<<edgeBlocks, TB>>>(dst);
    k_dinv_xn <<<nodeBlocks, TB>>>(x);
    k_l1_edges<<<edgeBlocks, TB>>>(src, dst);
    k_xform   <<<nodeBlocks, TB>>>(x, W1, b1, W2, out);
    k_l2_edges<<<edgeBlocks, TB>>>(src, dst, out);
    k_finish  <<<nodeBlocks, TB>>>(out, b2);
}

// round 8
// speedup vs baseline: 1.2941x; 1.0357x over previous
#include <cuda_runtime.h>

#define N_NODES 100000
#define N_EDGES 3200000

// ---- persistent device scratch (no allocations allowed) ----
__device__ int   g_deg [N_NODES];
__device__ float g_dinv[N_NODES];
__device__ float g_xn  [N_NODES * 4];   // x * dinv  (src-normalized features)
__device__ float g_agg [N_NODES * 4];   // layer-1 accumulator, init = xn (self loop)
__device__ float g_tn  [N_NODES * 2];   // t * dinv  (src-normalized layer-2 features)

// Vectorized no-return global reductions (one L2 message per 2/4 floats).
__device__ __forceinline__ void red_add_v4(float* p, float a, float b, float c, float d) {
    asm volatile("red.global.add.v4.f32 [%0], {%1,%2,%3,%4};"
                 :: "l"(p), "f"(a), "f"(b), "f"(c), "f"(d) : "memory");
}
__device__ __forceinline__ void red_add_v2(float* p, float a, float b) {
    asm volatile("red.global.add.v2.f32 [%0], {%1,%2};"
                 :: "l"(p), "f"(a), "f"(b) : "memory");
}
__device__ __forceinline__ void red_add_u32(int* p) {
    asm volatile("red.global.add.u32 [%0], 1;" :: "l"(p) : "memory");
}

// K1: degree of dst endpoints (4 edges / thread, int4-coalesced)
__global__ void k_deg(const int* __restrict__ dst) {
    int i = blockIdx.x * blockDim.x + threadIdx.x;
    if (i < N_EDGES / 4) {
        int4 d = reinterpret_cast<const int4*>(dst)[i];
        red_add_u32(&g_deg[d.x]);
        red_add_u32(&g_deg[d.y]);
        red_add_u32(&g_deg[d.z]);
        red_add_u32(&g_deg[d.w]);
    }
}

// K2: dinv = rsqrt(deg+1);  xn = x*dinv;  agg init = xn (layer-1 self loop,
// pre-dst-scale: a[v] = dinv*(sum_s xn[s] + xn[v]))
__global__ void k_dinv_xn(const float* __restrict__ x) {
    int i = blockIdx.x * blockDim.x + threadIdx.x;
    if (i >= N_NODES) return;
    float di = rsqrtf((float)(g_deg[i] + 1));
    g_dinv[i] = di;
    float4 xv = reinterpret_cast<const float4*>(x)[i];
    float4 xn = make_float4(xv.x * di, xv.y * di, xv.z * di, xv.w * di);
    reinterpret_cast<float4*>(g_xn)[i]  = xn;
    reinterpret_cast<float4*>(g_agg)[i] = xn;
}

// K3: layer-1 edges: agg[dst] += xn[src]  (dst factor deferred)
__global__ void k_l1_edges(const int* __restrict__ src, const int* __restrict__ dst) {
    int i = blockIdx.x * blockDim.x + threadIdx.x;
    if (i >= N_EDGES / 4) return;
    int4 s = reinterpret_cast<const int4*>(src)[i];
    int4 d = reinterpret_cast<const int4*>(dst)[i];
    const float4* xv = reinterpret_cast<const float4*>(g_xn);

    float4 v0 = xv[s.x];
    float4 v1 = xv[s.y];
    float4 v2 = xv[s.z];
    float4 v3 = xv[s.w];
    red_add_v4(&g_agg[4 * d.x], v0.x, v0.y, v0.z, v0.w);
    red_add_v4(&g_agg[4 * d.y], v1.x, v1.y, v1.z, v1.w);
    red_add_v4(&g_agg[4 * d.z], v2.x, v2.y, v2.z, v2.w);
    red_add_v4(&g_agg[4 * d.w], v3.x, v3.y, v3.z, v3.w);
}

// K4: per-node transform.
//   a = dinv*agg  (agg already contains self loop);  h = relu(a@W1+b1);
//   t = h@W2;  tn = t*dinv;  out init = tn (layer-2 self loop pre-dst-scale)
__global__ void k_xform(const float* __restrict__ W1, const float* __restrict__ b1,
                        const float* __restrict__ W2,
                        float* __restrict__ out) {
    int v = blockIdx.x * blockDim.x + threadIdx.x;
    if (v >= N_NODES) return;
    float di = g_dinv[v];
    float4 ag = reinterpret_cast<const float4*>(g_agg)[v];
    float a0 = ag.x * di;
    float a1 = ag.y * di;
    float a2 = ag.z * di;
    float a3 = ag.w * di;

    float t0 = 0.f, t1 = 0.f;
    #pragma unroll
    for (int j = 0; j < 16; j++) {
        float h = a0 * W1[j] + a1 * W1[16 + j] + a2 * W1[32 + j] + a3 * W1[48 + j] + b1[j];
        h = fmaxf(h, 0.f);
        t0 += h * W2[2 * j];
        t1 += h * W2[2 * j + 1];
    }
    float tn0 = t0 * di, tn1 = t1 * di;
    reinterpret_cast<float2*>(g_tn)[v] = make_float2(tn0, tn1);
    reinterpret_cast<float2*>(out)[v]  = make_float2(tn0, tn1);  // self-loop init
}

// K5: layer-2 edges: out[dst] += tn[src]  (dst factor deferred)
__global__ void k_l2_edges(const int* __restrict__ src, const int* __restrict__ dst,
                           float* __restrict__ out) {
    int i = blockIdx.x * blockDim.x + threadIdx.x;
    if (i >= N_EDGES / 4) return;
    int4 s = reinterpret_cast<const int4*>(src)[i];
    int4 d = reinterpret_cast<const int4*>(dst)[i];
    const float2* tv = reinterpret_cast<const float2*>(g_tn);

    float2 t0 = tv[s.x];
    float2 t1 = tv[s.y];
    float2 t2 = tv[s.z];
    float2 t3 = tv[s.w];
    red_add_v2(&out[2 * d.x], t0.x, t0.y);
    red_add_v2(&out[2 * d.y], t1.x, t1.y);
    red_add_v2(&out[2 * d.z], t2.x, t2.y);
    red_add_v2(&out[2 * d.w], t3.x, t3.y);
}

// K6: apply deferred dst factor + bias:  out = out*dinv + b2
__global__ void k_finish(float* __restrict__ out, const float* __restrict__ b2) {
    int v = blockIdx.x * blockDim.x + threadIdx.x;
    if (v >= N_NODES) return;
    float di = g_dinv[v];
    float2 o = reinterpret_cast<float2*>(out)[v];
    reinterpret_cast<float2*>(out)[v] =
        make_float2(o.x * di + b2[0], o.y * di + b2[1]);
}

extern "C" void kernel_launch(void* const* d_in, const int* in_sizes, int n_in,
                              void* d_out, int out_size) {
    const float* x   = (const float*)d_in[0];     // [N, 4]
    const int*   ei  = (const int*)  d_in[1];     // [2, E]
    const float* W1  = (const float*)d_in[2];     // [4, 16]
    const float* b1  = (const float*)d_in[3];     // [16]
    const float* W2  = (const float*)d_in[4];     // [16, 2]
    const float* b2  = (const float*)d_in[5];     // [2]
    float* out = (float*)d_out;                   // [N, 2]

    const int* src = ei;
    const int* dst = ei + N_EDGES;

    const int TB = 256;
    int nodeBlocks = (N_NODES + TB - 1) / TB;
    int edgeBlocks = (N_EDGES / 4 + TB - 1) / TB;

    // Zero only the degree accumulator (single small DMA memset node).
    void* degp = nullptr;
    cudaGetSymbolAddress(&degp, g_deg);
    cudaMemsetAsync(degp, 0, N_NODES * sizeof(int));

    k_deg     <<<edgeBlocks, TB>>>(dst);
    k_dinv_xn <<<nodeBlocks, TB>>>(x);
    k_l1_edges<<<edgeBlocks, TB>>>(src, dst);
    k_xform   <<<nodeBlocks, TB>>>(W1, b1, W2, out);
    k_l2_edges<<<edgeBlocks, TB>>>(src, dst, out);
    k_finish  <<<nodeBlocks, TB>>>(out, b2);
}